// round 16
// baseline (speedup 1.0000x reference)
#include <cuda_runtime.h>
#include <cuda_fp16.h>
#include <cstdint>

// ---------------- scratch (__device__ globals; no allocation) ----------------
__device__ float g_pool[1024 * 128];       // pooled conv2 features

// ---------------- helpers ----------------
__device__ __forceinline__ uint32_t smem_u32(const void* p) {
    uint32_t a;
    asm("{ .reg .u64 t; cvta.to.shared.u64 t, %1; cvt.u32.u64 %0, t; }" : "=r"(a) : "l"(p));
    return a;
}
__device__ __forceinline__ uint32_t pack_h2(float a, float b) {
    __half2 t = __floats2half2_rn(a, b);
    return *reinterpret_cast<uint32_t*>(&t);
}
__device__ __forceinline__ void ldmx4(uint32_t& r0, uint32_t& r1, uint32_t& r2, uint32_t& r3,
                                      uint32_t addr) {
    asm volatile("ldmatrix.sync.aligned.m8n8.x4.shared.b16 {%0,%1,%2,%3}, [%4];"
                 : "=r"(r0), "=r"(r1), "=r"(r2), "=r"(r3) : "r"(addr));
}
__device__ __forceinline__ void mma16816(float* c, const uint32_t* a, uint32_t b0, uint32_t b1) {
    asm volatile(
        "mma.sync.aligned.m16n8k16.row.col.f32.f16.f16.f32 "
        "{%0,%1,%2,%3}, {%4,%5,%6,%7}, {%8,%9}, {%0,%1,%2,%3};"
        : "+f"(c[0]), "+f"(c[1]), "+f"(c[2]), "+f"(c[3])
        : "r"(a[0]), "r"(a[1]), "r"(a[2]), "r"(a[3]), "r"(b0), "r"(b1));
}
__device__ __forceinline__ void half_bar(int barid) {
    asm volatile("bar.sync %0, %1;" :: "r"(barid), "r"(256) : "memory");
}

// ---------------- fused conv1+conv2+pool kernel (unchanged from R15) ----------------
static constexpr int B_OFF = 0;
static constexpr int ABUF_OFF = 149504;
static constexpr int ABUF_SZ = 29376;
static constexpr int SBIAS_OFF = 208256;
static constexpr int SPOOL_OFF = 208768;
static constexpr int C1W_OFF = 212864;
static constexpr int C1B_OFF = 216320;
static constexpr int SINH_OFF = 216576;
static constexpr int SMEM2_TOTAL = 228864;

__global__ __launch_bounds__(512, 1) void conv_fused_kernel(
    const float* __restrict__ x,
    const float* __restrict__ c1w, const float* __restrict__ c1b,
    const float* __restrict__ w, const float* __restrict__ bias) {
    extern __shared__ __align__(16) char smem[];
    uint32_t sbase = smem_u32(smem);
    float* sBias = reinterpret_cast<float*>(smem + SBIAS_OFF);
    float* sPool = reinterpret_cast<float*>(smem + SPOOL_OFF);
    __half2* c1wW = reinterpret_cast<__half2*>(smem + C1W_OFF);
    __half2* c1b2 = reinterpret_cast<__half2*>(smem + C1B_OFF);
    int tid = threadIdx.x, lane = tid & 31, wid = tid >> 5;
    int h = tid >> 8, ltid = tid & 255;
    int lwid = wid & 7;
    int m_idx = lwid & 3, n_idx = lwid >> 2;
    int barid = h + 1;

    for (int e = tid; e < 864; e += 512) {
        int b = e / 432, rem = e % 432;
        int rr = rem / 72, rem2 = rem % 72;
        int side = rem2 / 36, q = rem2 % 36;
        *reinterpret_cast<uint32_t*>(smem + ABUF_OFF + b * ABUF_SZ + rr * 4896 +
                                     (side ? 33 : 0) * 144 + q * 4) = 0u;
    }
    for (int e = tid; e < 73728; e += 512) {
        int n = e / 576, k = e - n * 576;
        int ic = k & 63, s = k >> 6;
        float v = w[n * 576 + ic * 9 + s];
        *reinterpret_cast<__half*>(smem + B_OFF + (n * 584 + k) * 2) = __float2half(v);
    }
    for (int e = tid; e < 864; e += 512) {
        int kt = e >> 5, wdx = e & 31;
        c1wW[kt * 32 + wdx] = __floats2half2_rn(c1w[(2 * wdx) * 27 + kt],
                                                c1w[(2 * wdx + 1) * 27 + kt]);
    }
    if (tid < 32) c1b2[tid] = __floats2half2_rn(c1b[2 * tid], c1b[2 * tid + 1]);
    if (tid < 128) sBias[tid] = bias[tid];
    __syncthreads();

    uint32_t aThr = (uint32_t)((lane & 15) * 144 + ((lane >> 4) & 1) * 16);
    uint32_t bThr = (uint32_t)(((((lane >> 4) & 1) * 8 + (lane & 7)) * 584 +
                                ((lane >> 3) & 1) * 8) * 2 + n_idx * 74752);
    uint32_t abuf = sbase + ABUF_OFF + (uint32_t)(h * ABUF_SZ);
    char* abufp = smem + ABUF_OFF + h * ABUF_SZ;
    const __half* sI = reinterpret_cast<const __half*>(smem + SINH_OFF + h * 6144);
    uint32_t* sInW = reinterpret_cast<uint32_t*>(smem + SINH_OFF + h * 6144);

    int c1_r0 = ltid >> 7;
    int c1_ocg = (ltid >> 5) & 3;
    int c1_px = ltid & 31;

    int K = (1024 - blockIdx.x + 147) / 148;
    int kmid = (K + 1) >> 1;
    int kbeg = h ? kmid : 0;
    int kend = h ? K : kmid;

    for (int kk = kbeg; kk < kend; kk++) {
        int img = blockIdx.x + 148 * kk;
        {
            const float4* gx4 = reinterpret_cast<const float4*>(x + (size_t)img * 3072);
#pragma unroll
            for (int i = 0; i < 3; i++) {
                int e = ltid + i * 256;
                float4 v = gx4[e];
                sInW[2 * e] = pack_h2(v.x, v.y);
                sInW[2 * e + 1] = pack_h2(v.z, v.w);
            }
        }
        float pool[8][2];
#pragma unroll
        for (int j = 0; j < 8; j++) { pool[j][0] = 0.f; pool[j][1] = 0.f; }

        for (int t = 0; t < 8; t++) {
            half_bar(barid);
            {
                __half2 z2 = __float2half2_rn(0.f);
                __half2 acc[3][8];
#pragma unroll
                for (int j = 0; j < 8; j++) {
                    __half2 b = c1b2[c1_ocg * 8 + j];
#pragma unroll
                    for (int i = 0; i < 3; i++) acc[i][j] = b;
                }
#pragma unroll
                for (int ic = 0; ic < 3; ic++) {
#pragma unroll
                    for (int ky = 0; ky < 3; ky++) {
                        __half2 iv[3][3];
#pragma unroll
                        for (int i = 0; i < 3; i++) {
                            int y = 4 * t + c1_r0 + 2 * i + ky - 2;
#pragma unroll
                            for (int dx = 0; dx < 3; dx++) {
                                int xx = c1_px + dx - 1;
                                __half v = __float2half(0.f);
                                if ((unsigned)y < 32u && (unsigned)xx < 32u)
                                    v = sI[ic * 1024 + y * 32 + xx];
                                iv[i][dx] = __half2half2(v);
                            }
                        }
#pragma unroll
                        for (int kx = 0; kx < 3; kx++) {
                            int kt = ic * 9 + ky * 3 + kx;
                            const __half2* wp = c1wW + kt * 32 + c1_ocg * 8;
                            __half2 w8[8];
#pragma unroll
                            for (int j = 0; j < 8; j++) w8[j] = wp[j];
#pragma unroll
                            for (int i = 0; i < 3; i++)
#pragma unroll
                                for (int j = 0; j < 8; j++)
                                    acc[i][j] = __hfma2(iv[i][kx], w8[j], acc[i][j]);
                        }
                    }
                }
#pragma unroll
                for (int i = 0; i < 3; i++) {
                    int row = c1_r0 + 2 * i;
                    int gy = 4 * t + row - 1;
                    char* ap = abufp + row * 4896 + (c1_px + 1) * 144 + c1_ocg * 32;
                    uint4 v0, v1;
                    if ((unsigned)gy < 32u) {
                        __half2 o[8];
#pragma unroll
                        for (int j = 0; j < 8; j++) o[j] = __hmax2(acc[i][j], z2);
                        v0 = *reinterpret_cast<uint4*>(&o[0]);
                        v1 = *reinterpret_cast<uint4*>(&o[4]);
                    } else {
                        v0 = make_uint4(0u, 0u, 0u, 0u);
                        v1 = v0;
                    }
                    *reinterpret_cast<uint4*>(ap) = v0;
                    *reinterpret_cast<uint4*>(ap + 16) = v1;
                }
            }
            half_bar(barid);

            float acc[2][8][4];
#pragma unroll
            for (int f = 0; f < 2; f++)
#pragma unroll
                for (int j = 0; j < 8; j++)
#pragma unroll
                    for (int q = 0; q < 4; q++) acc[f][j][q] = 0.f;

            uint32_t aBase = abuf + (uint32_t)(m_idx * 4896) + aThr;
            uint32_t bBase = sbase + B_OFF + bThr;
#pragma unroll
            for (int s = 0; s < 9; s++) {
                const uint32_t doff = (uint32_t)((s / 3) * 4896 + (s % 3) * 144);
#pragma unroll
                for (int ks = 0; ks < 4; ks++) {
                    uint32_t a[2][4];
#pragma unroll
                    for (int f = 0; f < 2; f++)
                        ldmx4(a[f][0], a[f][1], a[f][2], a[f][3],
                              aBase + doff + (uint32_t)(f * 2304 + ks * 32));
                    uint32_t kofs = (uint32_t)(s * 128 + ks * 32);
#pragma unroll
                    for (int fp = 0; fp < 4; fp++) {
                        uint32_t r0, r1, r2, r3;
                        ldmx4(r0, r1, r2, r3, bBase + (uint32_t)(fp * 18688) + kofs);
#pragma unroll
                        for (int f = 0; f < 2; f++) {
                            mma16816(acc[f][fp * 2], a[f], r0, r1);
                            mma16816(acc[f][fp * 2 + 1], a[f], r2, r3);
                        }
                    }
                }
            }
#pragma unroll
            for (int j = 0; j < 8; j++) {
                float b0 = sBias[n_idx * 64 + j * 8 + (lane & 3) * 2];
                float b1 = sBias[n_idx * 64 + j * 8 + (lane & 3) * 2 + 1];
                pool[j][0] += fmaxf(acc[0][j][0] + b0, 0.f) + fmaxf(acc[0][j][2] + b0, 0.f) +
                              fmaxf(acc[1][j][0] + b0, 0.f) + fmaxf(acc[1][j][2] + b0, 0.f);
                pool[j][1] += fmaxf(acc[0][j][1] + b1, 0.f) + fmaxf(acc[0][j][3] + b1, 0.f) +
                              fmaxf(acc[1][j][1] + b1, 0.f) + fmaxf(acc[1][j][3] + b1, 0.f);
            }
        }
#pragma unroll
        for (int off = 4; off <= 16; off <<= 1)
#pragma unroll
            for (int j = 0; j < 8; j++) {
                pool[j][0] += __shfl_xor_sync(0xffffffffu, pool[j][0], off);
                pool[j][1] += __shfl_xor_sync(0xffffffffu, pool[j][1], off);
            }
        if (lane < 4) {
            float* sp = sPool + wid * 64;
#pragma unroll
            for (int j = 0; j < 8; j++) {
                sp[j * 8 + lane * 2] = pool[j][0];
                sp[j * 8 + lane * 2 + 1] = pool[j][1];
            }
        }
        half_bar(barid);
        if (ltid < 128) {
            int ni = ltid >> 6, col = ltid & 63;
            float s = 0.f;
#pragma unroll
            for (int m = 0; m < 4; m++) s += sPool[(h * 8 + ni * 4 + m) * 64 + col];
            g_pool[img * 128 + ni * 64 + col] = s * (1.f / 1024.f);
        }
    }
}

// ---------------- fused tail (512 threads, node-split) ----------------
static constexpr int TP_POOL = 0;       // 32 x 128
static constexpr int TP_H    = 4096;    // 32 x 256 (reused as sage2 partials)
static constexpr int TP_O1   = 12288;   // 32 x 256
static constexpr int TP_CS   = 20480;   // 256
static constexpr int TP_B2   = 20736;   // 256
static constexpr int TP_MASK = 20992;   // 32
static constexpr int TAIL_SMEM = 21024 * 4;

__global__ __launch_bounds__(512) void tail_kernel(
    const float* __restrict__ fc_w, const float* __restrict__ fc_b,
    const float* __restrict__ mask,
    const float* __restrict__ s1_lw, const float* __restrict__ s1_lb,
    const float* __restrict__ s1_rw,
    const float* __restrict__ s2_lw, const float* __restrict__ s2_lb,
    const float* __restrict__ s2_rw,
    float* __restrict__ out) {
    extern __shared__ float sm[];
    float* sPool = sm + TP_POOL;
    float* sH    = sm + TP_H;
    float* sO1   = sm + TP_O1;
    float* sCs   = sm + TP_CS;
    float* sB2   = sm + TP_B2;
    float* sMask = sm + TP_MASK;
    int b = blockIdx.x, tid = threadIdx.x;

    for (int e = tid; e < 4096; e += 512) sPool[e] = g_pool[b * 4096 + e];
    if (tid < 32) sMask[tid] = mask[b * 32 + tid];
    __syncthreads();

    // fc: o = tid&255, node-half nh = tid>>8 (16 nodes each)
    {
        int o = tid & 255, nh = tid >> 8;
        int n0 = nh * 16;
        float acc[16];
#pragma unroll
        for (int n = 0; n < 16; n++) acc[n] = 0.f;
        const float4* wrow = reinterpret_cast<const float4*>(fc_w + o * 128);
#pragma unroll 4
        for (int k4 = 0; k4 < 32; k4++) {
            float4 wv = wrow[k4];
#pragma unroll
            for (int n = 0; n < 16; n++) {
                float4 hv = *reinterpret_cast<const float4*>(sPool + (n0 + n) * 128 + k4 * 4);
                acc[n] += wv.x * hv.x + wv.y * hv.y + wv.z * hv.z + wv.w * hv.w;
            }
        }
        float fb = fc_b[o];
#pragma unroll
        for (int n = 0; n < 16; n++) sH[(n0 + n) * 256 + o] = (acc[n] + fb) * sMask[n0 + n];
    }
    __syncthreads();
    if (tid < 256) {
        float s = 0.f;
#pragma unroll
        for (int n = 0; n < 32; n++) s += sH[n * 256 + tid];
        sCs[tid] = s;
    }
    __syncthreads();

    // sage1: o = tid&255, node-half nh
    {
        int o = tid & 255, nh = tid >> 8;
        int n0 = nh * 16;
        float acc[16];
#pragma unroll
        for (int n = 0; n < 16; n++) acc[n] = 0.f;
        float bacc = 0.f;
        const float4* lw4 = reinterpret_cast<const float4*>(s1_lw + o * 256);
        const float4* rw4 = reinterpret_cast<const float4*>(s1_rw + o * 256);
#pragma unroll 2
        for (int k4 = 0; k4 < 64; k4++) {
            float4 lw = lw4[k4], rw = rw4[k4];
            float4 cs = *reinterpret_cast<const float4*>(sCs + k4 * 4);
            bacc += cs.x * lw.x + cs.y * lw.y + cs.z * lw.z + cs.w * lw.w;
            float4 wc;
            wc.x = rw.x - lw.x * (1.f / 31.f); wc.y = rw.y - lw.y * (1.f / 31.f);
            wc.z = rw.z - lw.z * (1.f / 31.f); wc.w = rw.w - lw.w * (1.f / 31.f);
#pragma unroll
            for (int n = 0; n < 16; n++) {
                float4 hv = *reinterpret_cast<const float4*>(sH + (n0 + n) * 256 + k4 * 4);
                acc[n] += wc.x * hv.x + wc.y * hv.y + wc.z * hv.z + wc.w * hv.w;
            }
        }
        float base = s1_lb[o] + bacc * (1.f / 31.f);
#pragma unroll
        for (int n = 0; n < 16; n++)
            sO1[(n0 + n) * 256 + o] = fmaxf(base + acc[n], 0.f);
    }
    __syncthreads();
    if (tid < 256) {
        float s = 0.f;
#pragma unroll
        for (int n = 0; n < 32; n++) s += sO1[n * 256 + tid];
        sCs[tid] = s;
    }
    __syncthreads();

    // sage2: o2 = tid&127, kh = (tid>>7)&1 (k half), nh = tid>>8 (node half)
    {
        int o2 = tid & 127, kh = (tid >> 7) & 1, nh = tid >> 8;
        int n0 = nh * 16;
        float acc[16];
#pragma unroll
        for (int n = 0; n < 16; n++) acc[n] = 0.f;
        float bacc = 0.f;
        const float4* lw4 = reinterpret_cast<const float4*>(s2_lw + o2 * 256 + kh * 128);
        const float4* rw4 = reinterpret_cast<const float4*>(s2_rw + o2 * 256 + kh * 128);
        const float* csb = sCs + kh * 128;
        const float* o1b = sO1 + kh * 128;
#pragma unroll 2
        for (int k4 = 0; k4 < 32; k4++) {
            float4 lw = lw4[k4], rw = rw4[k4];
            float4 cs = *reinterpret_cast<const float4*>(csb + k4 * 4);
            bacc += cs.x * lw.x + cs.y * lw.y + cs.z * lw.z + cs.w * lw.w;
            float4 wc;
            wc.x = rw.x - lw.x * (1.f / 31.f); wc.y = rw.y - lw.y * (1.f / 31.f);
            wc.z = rw.z - lw.z * (1.f / 31.f); wc.w = rw.w - lw.w * (1.f / 31.f);
#pragma unroll
            for (int n = 0; n < 16; n++) {
                float4 hv = *reinterpret_cast<const float4*>(o1b + (n0 + n) * 256 + k4 * 4);
                acc[n] += wc.x * hv.x + wc.y * hv.y + wc.z * hv.z + wc.w * hv.w;
            }
        }
#pragma unroll
        for (int n = 0; n < 16; n++) sH[(n0 + n) * 256 + kh * 128 + o2] = acc[n];
        if (nh == 0) sB2[kh * 128 + o2] = bacc;
    }
    __syncthreads();
    for (int e = tid; e < 4096; e += 512) {
        int n = e >> 7, o2 = e & 127;
        float v = sH[n * 256 + o2] + sH[n * 256 + o2 + 128];
        float base = s2_lb[o2] + (sB2[o2] + sB2[o2 + 128]) * (1.f / 31.f);
        out[(b * 32 + n) * 128 + o2] = base + v;
    }
}

// ---------------- launch ----------------
extern "C" void kernel_launch(void* const* d_in, const int* in_sizes, int n_in,
                              void* d_out, int out_size) {
    const float* x       = (const float*)d_in[0];
    const float* mask    = (const float*)d_in[1];
    const float* conv1_w = (const float*)d_in[2];
    const float* conv1_b = (const float*)d_in[3];
    const float* conv2_w = (const float*)d_in[4];
    const float* conv2_b = (const float*)d_in[5];
    const float* fc_w    = (const float*)d_in[6];
    const float* fc_b    = (const float*)d_in[7];
    const float* s1_lw   = (const float*)d_in[8];
    const float* s1_lb   = (const float*)d_in[9];
    const float* s1_rw   = (const float*)d_in[10];
    const float* s2_lw   = (const float*)d_in[11];
    const float* s2_lb   = (const float*)d_in[12];
    const float* s2_rw   = (const float*)d_in[13];
    float* out = (float*)d_out;

    cudaFuncSetAttribute(conv_fused_kernel, cudaFuncAttributeMaxDynamicSharedMemorySize,
                         SMEM2_TOTAL);
    cudaFuncSetAttribute(tail_kernel, cudaFuncAttributeMaxDynamicSharedMemorySize, TAIL_SMEM);

    conv_fused_kernel<<<148, 512, SMEM2_TOTAL>>>(x, conv1_w, conv1_b, conv2_w, conv2_b);
    tail_kernel<<<32, 512, TAIL_SMEM>>>(fc_w, fc_b, mask, s1_lw, s1_lb, s1_rw,
                                        s2_lw, s2_lb, s2_rw, out);
}